// round 13
// baseline (speedup 1.0000x reference)
#include <cuda_runtime.h>
#include <cuda_bf16.h>

#define NN 100000
#define NE 1600000
#define NT_EDGE 1700000   // edges + self loops
#define NG 256
#define NBLK 391          // ceil(NN/256)

// ---------------- scratch (static device allocations; no runtime alloc) ----
__device__ int   g_cnt[NN];               // in-degree WITHOUT self loop
__device__ int   g_rank[NE];              // within-bucket rank of each edge
__device__ int   g_rowptr[NN + 1];
__device__ volatile int g_flag[NBLK];     // lookback state: 0 none, 1 agg, 2 prefix
__device__ volatile int g_aggv[NBLK];
__device__ volatile int g_incv[NBLK];
__device__ __align__(16) int2  g_edata[NT_EDGE];        // {src, f2i(norm)} by dst
__device__ __align__(256) __nv_bfloat16 g_xpb[NN * 64];  // x padded, bf16, stride 64 (1 line)
__device__ __align__(256) __nv_bfloat16 g_h1b[NN * 64];  // layer1 out bf16 (54 real)
__device__ __align__(256) __nv_bfloat16 g_h2b[NN * 128]; // layer2 out bf16 (108 real)
__device__ __align__(256) __nv_bfloat16 g_h3b[NN * 224]; // layer3 out bf16 (216 real)
__device__ __align__(256) __nv_bfloat16 g_aggb[NN * 112];// aggregation out bf16
__device__ __align__(16) float g_Wp1[56 * 64];
__device__ __align__(16) float g_Wp2[56 * 128];
__device__ __align__(16) float g_Wp3[112 * 224];
__device__ float g_bp1[64], g_bp2[128], g_bp3[224];
__device__ float g_pool[NG * 216];
__device__ int   g_goff[NG + 1];
__device__ float g_g1[NG * 1024];

// ---------------- zero pass (must precede merged atomics) ----------------
__global__ void k_zero() {
    int i = blockIdx.x * blockDim.x + threadIdx.x;
    if (i < NN) g_cnt[i] = 0;
    if (i < NBLK) g_flag[i] = 0;
}

// ---------------- merged preprocessing: counts(+rank) + boundaries + padW + xpad
#define PW1 (56 * 64 + 64)
#define PW2 (56 * 128 + 128)
#define PW3 (112 * 224 + 224)
#define M0 NE
#define M1 (M0 + NN)
#define M2 (M1 + PW1)
#define M3 (M2 + PW2)
#define M4 (M3 + PW3)
#define M5 (M4 + NN * 8)

__device__ __forceinline__ void padw_one(int j, const float* W, const float* b,
                                         float* Wp, float* bp, int K, int C,
                                         int KPAD, int CPAD) {
    int tot = KPAD * CPAD;
    if (j < tot) {
        int cc = j % CPAD, kk = j / CPAD;
        Wp[j] = (cc < C && kk < K) ? W[kk * C + cc] : 0.f;
    } else {
        int cc = j - tot;
        bp[cc] = (cc < C) ? b[cc] : 0.f;
    }
}

__global__ void k_merged(const int* __restrict__ ei, const int* __restrict__ batch,
                         const float* __restrict__ x,
                         const float* __restrict__ W1, const float* __restrict__ b1,
                         const float* __restrict__ W2, const float* __restrict__ b2,
                         const float* __restrict__ W3, const float* __restrict__ b3) {
    int i = blockIdx.x * blockDim.x + threadIdx.x;
    if (i < M0) {
        g_rank[i] = atomicAdd(&g_cnt[ei[NE + i]], 1);   // count AND capture rank
    } else if (i < M1) {
        int j = i - M0;
        int bi = batch[j];
        int bprev = (j > 0) ? batch[j - 1] : -1;
        for (int g = bprev + 1; g <= bi; g++) g_goff[g] = j;
        if (j == NN - 1)
            for (int g = bi + 1; g <= NG; g++) g_goff[g] = NN;
    } else if (i < M2) {
        padw_one(i - M1, W1, b1, g_Wp1, g_bp1, 54, 54, 56, 64);
    } else if (i < M3) {
        padw_one(i - M2, W2, b2, g_Wp2, g_bp2, 54, 108, 56, 128);
    } else if (i < M4) {
        padw_one(i - M3, W3, b3, g_Wp3, g_bp3, 108, 216, 112, 224);
    } else if (i < M5) {
        int j = i - M4;
        int r = j >> 3, cw = (j & 7) * 8;
        __nv_bfloat16 tmp[8];
#pragma unroll
        for (int t = 0; t < 8; t++) {
            int c = cw + t;
            tmp[t] = __float2bfloat16((c < 54) ? x[r * 54 + c] : 0.f);
        }
        *(uint4*)&g_xpb[r * 64 + cw] = *(uint4*)tmp;
    }
}

// ---------------- single-kernel decoupled-lookback exclusive scan ---------
// rowptr = exclusive_scan(cnt + 1). All NBLK blocks fit in one wave.
__global__ void k_scan() {
    __shared__ int p[256];
    __shared__ int s_excl;
    int b = blockIdx.x, t = threadIdx.x;
    int i = b * 256 + t;
    int v = (i < NN) ? g_cnt[i] + 1 : 0;    // +1 self loop
    p[t] = v;
    __syncthreads();
    for (int off = 1; off < 256; off <<= 1) {
        int u = (t >= off) ? p[t - off] : 0;
        __syncthreads();
        p[t] += u;
        __syncthreads();
    }
    int total = p[255];
    if (t == 0) {
        if (b == 0) {
            g_incv[0] = total;
            __threadfence();
            g_flag[0] = 2;
            s_excl = 0;
        } else {
            g_aggv[b] = total;
            __threadfence();
            g_flag[b] = 1;
            int excl = 0;
            for (int j = b - 1; j >= 0; j--) {
                int f;
                do { f = g_flag[j]; } while (f == 0);
                if (f == 2) { excl += g_incv[j]; break; }
                excl += g_aggv[j];
            }
            g_incv[b] = excl + total;
            __threadfence();
            g_flag[b] = 2;
            s_excl = excl;
        }
    }
    __syncthreads();
    int excl_t = p[t] - v + s_excl;
    if (i < NN) g_rowptr[i] = excl_t;
    if (i == NN - 1) g_rowptr[NN] = excl_t + v;
}

// ---------------- fill (no atomics: rank precomputed) ----------------
__global__ void k_fill(const int* __restrict__ ei) {
    int i = blockIdx.x * blockDim.x + threadIdx.x;
    if (i >= NT_EDGE) return;
    int r, c, rk;
    if (i < NE) { r = ei[i]; c = ei[NE + i]; rk = g_rank[i]; }
    else        { r = c = i - NE; rk = g_cnt[c]; }   // self loop: last slot
    float nrm = rsqrtf((float)(g_cnt[r] + 1) * (float)(g_cnt[c] + 1));
    g_edata[g_rowptr[c] + rk] = make_int2(r, __float_as_int(nrm));
}

// ---------------- aggregation (bf16 gather, fp32 acc, bf16 out) -----------
__device__ __forceinline__ void acc8(float acc[8], float nrm, uint4 t) {
    float2 f0 = __bfloat1622float2(*(__nv_bfloat162*)&t.x);
    float2 f1 = __bfloat1622float2(*(__nv_bfloat162*)&t.y);
    float2 f2 = __bfloat1622float2(*(__nv_bfloat162*)&t.z);
    float2 f3 = __bfloat1622float2(*(__nv_bfloat162*)&t.w);
    acc[0] += nrm * f0.x; acc[1] += nrm * f0.y;
    acc[2] += nrm * f1.x; acc[3] += nrm * f1.y;
    acc[4] += nrm * f2.x; acc[5] += nrm * f2.y;
    acc[6] += nrm * f3.x; acc[7] += nrm * f3.y;
}

__device__ __forceinline__ uint4 pack8(const float acc[8]) {
    uint4 r;
    *(__nv_bfloat162*)&r.x = __float22bfloat162_rn(make_float2(acc[0], acc[1]));
    *(__nv_bfloat162*)&r.y = __float22bfloat162_rn(make_float2(acc[2], acc[3]));
    *(__nv_bfloat162*)&r.z = __float22bfloat162_rn(make_float2(acc[4], acc[5]));
    *(__nv_bfloat162*)&r.w = __float22bfloat162_rn(make_float2(acc[6], acc[7]));
    return r;
}

// 64-bf16 rows (128B = 1 line). 8 edges/warp-iter. bf16 out rows stride 64.
__global__ void k_agg64b(const __nv_bfloat16* __restrict__ in,
                         __nv_bfloat16* __restrict__ out) {
    int w = (blockIdx.x * blockDim.x + threadIdx.x) >> 5;
    int lane = threadIdx.x & 31;
    if (w >= NN) return;
    int q = lane >> 3, sl = lane & 7;
    int e0 = g_rowptr[w], e1 = g_rowptr[w + 1];
    float acc[8];
#pragma unroll
    for (int j = 0; j < 8; j++) acc[j] = 0.f;
    for (int e = e0; e < e1; e += 8) {
        int i0 = e + q, i1 = e + 4 + q;
        bool v0 = i0 < e1, v1 = i1 < e1;
        int2 ed0 = __ldg(&g_edata[v0 ? i0 : e]);
        int2 ed1 = __ldg(&g_edata[v1 ? i1 : e]);
        float n0 = v0 ? __int_as_float(ed0.y) : 0.f;
        float n1 = v1 ? __int_as_float(ed1.y) : 0.f;
        const uint4* s0 = (const uint4*)(in + (long)ed0.x * 64);
        const uint4* s1 = (const uint4*)(in + (long)ed1.x * 64);
        uint4 t0 = __ldg(&s0[sl]);
        uint4 t1 = __ldg(&s1[sl]);
        acc8(acc, n0, t0);
        acc8(acc, n1, t1);
    }
#pragma unroll
    for (int j = 0; j < 8; j++) {
        acc[j] += __shfl_xor_sync(0xffffffffu, acc[j], 8);
        acc[j] += __shfl_xor_sync(0xffffffffu, acc[j], 16);
    }
    if (q == 0)   // all 8 sl active: full 64-el row (cols 54-63 are zeros)
        ((uint4*)(out + (long)w * 64))[sl] = pack8(acc);
}

// 128-bf16 rows (256B = 2 lines). 4 edges/warp-iter. bf16 out rows stride 112.
__global__ void k_agg128b(const __nv_bfloat16* __restrict__ in,
                          __nv_bfloat16* __restrict__ out) {
    int w = (blockIdx.x * blockDim.x + threadIdx.x) >> 5;
    int lane = threadIdx.x & 31;
    if (w >= NN) return;
    int half = lane >> 4, sl = lane & 15;
    int e0 = g_rowptr[w], e1 = g_rowptr[w + 1];
    float acc[8];
#pragma unroll
    for (int j = 0; j < 8; j++) acc[j] = 0.f;
    for (int e = e0; e < e1; e += 4) {
        int i0 = e + half, i1 = e + 2 + half;
        bool v0 = i0 < e1, v1 = i1 < e1;
        int2 ed0 = __ldg(&g_edata[v0 ? i0 : e]);
        int2 ed1 = __ldg(&g_edata[v1 ? i1 : e]);
        float n0 = v0 ? __int_as_float(ed0.y) : 0.f;
        float n1 = v1 ? __int_as_float(ed1.y) : 0.f;
        const uint4* s0 = (const uint4*)(in + (long)ed0.x * 128);
        const uint4* s1 = (const uint4*)(in + (long)ed1.x * 128);
        uint4 t0 = __ldg(&s0[sl]);
        uint4 t1 = __ldg(&s1[sl]);
        acc8(acc, n0, t0);
        acc8(acc, n1, t1);
    }
#pragma unroll
    for (int j = 0; j < 8; j++)
        acc[j] += __shfl_xor_sync(0xffffffffu, acc[j], 16);
    if (half == 0 && sl < 14)   // 112-el row
        ((uint4*)(out + (long)w * 112))[sl] = pack8(acc);
}

// ---------------- tf32 tensor-core GEMM (A staged from bf16), bf16 out ----
__device__ __forceinline__ unsigned f2tf(float v) {
    unsigned u;
    asm("cvt.rna.tf32.f32 %0, %1;" : "=r"(u) : "f"(v));
    return u;
}

__device__ __forceinline__ void mma_tf32(float c[4], const unsigned a[4], const unsigned b[2]) {
    asm volatile(
        "mma.sync.aligned.m16n8k8.row.col.f32.tf32.tf32.f32 "
        "{%0,%1,%2,%3}, {%4,%5,%6,%7}, {%8,%9}, {%0,%1,%2,%3};\n"
        : "+f"(c[0]), "+f"(c[1]), "+f"(c[2]), "+f"(c[3])
        : "r"(a[0]), "r"(a[1]), "r"(a[2]), "r"(a[3]), "r"(b[0]), "r"(b[1]));
}

// A: bf16 rows of stride SRCSTR (>= KPAD), first KPAD cols used.
template <int KPAD, int CPAD, int SRCSTR>
__global__ __launch_bounds__(256)
void k_gemm_mma(const __nv_bfloat16* __restrict__ A, const float* __restrict__ W,
                const float* __restrict__ bias, __nv_bfloat16* __restrict__ out) {
    extern __shared__ float sm[];
    constexpr int ASTR = KPAD + 2;
    constexpr int WSTR = CPAD + 8;
    constexpr int KCH = 56;
    constexpr int NTILES = CPAD / 32;
    float* As = sm;                       // [64][ASTR]
    float* Ws = sm + 64 * ASTR;           // [KCH][WSTR]

    int tid = threadIdx.x;
    int w = tid >> 5, lane = tid & 31;
    int g = lane >> 2, ctg = lane & 3;
    int wm = w & 1, wn = w >> 1;
    int row0 = blockIdx.x * 64;

    float c[2][NTILES][4];
#pragma unroll
    for (int mt = 0; mt < 2; mt++)
#pragma unroll
        for (int nt = 0; nt < NTILES; nt++)
#pragma unroll
            for (int i = 0; i < 4; i++) c[mt][nt][i] = 0.f;

    // stage A: bf16 -> tf32 (KPAD % 8 == 0, 8 els per thread-chunk)
    for (int i = tid * 8; i < 64 * KPAD; i += 256 * 8) {
        int r = i / KPAD, k = i % KPAD;
        uint4 v = make_uint4(0u, 0u, 0u, 0u);
        if (row0 + r < NN) v = *(const uint4*)&A[(long)(row0 + r) * SRCSTR + k];
        const __nv_bfloat16* hb = (const __nv_bfloat16*)&v;
        float* o = As + r * ASTR + k;
#pragma unroll
        for (int t = 0; t < 8; t++)
            o[t] = __uint_as_float(f2tf(__bfloat162float(hb[t])));
    }

#pragma unroll 1
    for (int kc = 0; kc < KPAD; kc += KCH) {
        constexpr int kchunk = (KPAD < KCH) ? KPAD : KCH;
        for (int i = tid * 4; i < kchunk * CPAD; i += 256 * 4) {
            int kk = i / CPAD, cc = i % CPAD;
            float4 v = *(const float4*)&W[(long)(kc + kk) * CPAD + cc];
            float4 t;
            t.x = __uint_as_float(f2tf(v.x));
            t.y = __uint_as_float(f2tf(v.y));
            t.z = __uint_as_float(f2tf(v.z));
            t.w = __uint_as_float(f2tf(v.w));
            *(float4*)&Ws[kk * WSTR + cc] = t;
        }
        __syncthreads();

#pragma unroll
        for (int ks = 0; ks < kchunk; ks += 8) {
            unsigned a[2][4];
#pragma unroll
            for (int mt = 0; mt < 2; mt++) {
                int ar = wm * 32 + mt * 16;
                int kb = kc + ks + ctg;
                a[mt][0] = __float_as_uint(As[(ar + g) * ASTR + kb]);
                a[mt][1] = __float_as_uint(As[(ar + g + 8) * ASTR + kb]);
                a[mt][2] = __float_as_uint(As[(ar + g) * ASTR + kb + 4]);
                a[mt][3] = __float_as_uint(As[(ar + g + 8) * ASTR + kb + 4]);
            }
            unsigned b[NTILES][2];
#pragma unroll
            for (int nt = 0; nt < NTILES; nt++) {
                int col = wn * (CPAD / 4) + nt * 8 + g;
                b[nt][0] = __float_as_uint(Ws[(ks + ctg) * WSTR + col]);
                b[nt][1] = __float_as_uint(Ws[(ks + ctg + 4) * WSTR + col]);
            }
#pragma unroll
            for (int mt = 0; mt < 2; mt++)
#pragma unroll
                for (int nt = 0; nt < NTILES; nt++)
                    mma_tf32(c[mt][nt], a[mt], b[nt]);
        }
        __syncthreads();
    }

#pragma unroll
    for (int mt = 0; mt < 2; mt++) {
        int r0 = row0 + wm * 32 + mt * 16 + g;
#pragma unroll
        for (int nt = 0; nt < NTILES; nt++) {
            int col = wn * (CPAD / 4) + nt * 8 + 2 * ctg;
            float b0 = bias[col], b1 = bias[col + 1];
            if (r0 < NN)
                *(__nv_bfloat162*)&out[(long)r0 * CPAD + col] =
                    __float22bfloat162_rn(make_float2(
                        fmaxf(c[mt][nt][0] + b0, 0.f), fmaxf(c[mt][nt][1] + b1, 0.f)));
            if (r0 + 8 < NN)
                *(__nv_bfloat162*)&out[(long)(r0 + 8) * CPAD + col] =
                    __float22bfloat162_rn(make_float2(
                        fmaxf(c[mt][nt][2] + b0, 0.f), fmaxf(c[mt][nt][3] + b1, 0.f)));
        }
    }
}

// ---------------- pooling (bf16 in, fp32 accumulate) ----------------
__global__ void k_pool() {    // grid NG, block 224
    int g = blockIdx.x, f = threadIdx.x;
    if (f >= 216) return;
    int v0 = g_goff[g], v1 = g_goff[g + 1];
    float s = 0.f;
    for (int v = v0; v < v1; v++) s += __bfloat162float(g_h3b[(long)v * 224 + f]);
    float cnt = (float)(v1 - v0);
    g_pool[g * 216 + f] = s / fmaxf(cnt, 1.f);
}

// ---------------- tiled MLP head (fp32) ----------------
__global__ __launch_bounds__(256) void k_mlp1(const float* __restrict__ Wf1,
                                              const float* __restrict__ bf1) {
    extern __shared__ float smm[];
    float* Pt = smm;            // [64][216]
    float* Wt = smm + 64 * 216; // [216][32]
    int b = blockIdx.x, t = threadIdx.x;
    int bi = b >> 5, bj = b & 31;
    int g0 = bi * 64, c0 = bj * 32;
    for (int i = t; i < 64 * 216; i += 256) {
        int r = i / 216, k = i - r * 216;
        Pt[i] = g_pool[(g0 + r) * 216 + k];
    }
    for (int i = t; i < 216 * 32; i += 256) {
        int k = i >> 5, c = i & 31;
        Wt[i] = Wf1[k * 1024 + c0 + c];
    }
    __syncthreads();
    int c = t & 31, rb = t >> 5;
    float acc[8];
#pragma unroll
    for (int j = 0; j < 8; j++) acc[j] = 0.f;
    for (int k = 0; k < 216; k++) {
        float wv = Wt[k * 32 + c];
#pragma unroll
        for (int j = 0; j < 8; j++)
            acc[j] += Pt[(rb + 8 * j) * 216 + k] * wv;
    }
    float bias = bf1[c0 + c];
#pragma unroll
    for (int j = 0; j < 8; j++)
        g_g1[(g0 + rb + 8 * j) * 1024 + c0 + c] = fmaxf(acc[j] + bias, 0.f);
}

__global__ __launch_bounds__(256) void k_mlp2(const float* __restrict__ Wf2,
                                              const float* __restrict__ bf2,
                                              float* __restrict__ out) {
    __shared__ float At[64 * 128];   // 32KB
    __shared__ float Wt[128 * 32];   // 16KB
    int b = blockIdx.x, t = threadIdx.x;
    int bi = b >> 2, bj = b & 3;
    int g0 = bi * 64, c0 = bj * 32;
    int c = t & 31, rb = t >> 5;
    float acc[8];
#pragma unroll
    for (int j = 0; j < 8; j++) acc[j] = 0.f;
    for (int k0 = 0; k0 < 1024; k0 += 128) {
        for (int i = t; i < 64 * 128; i += 256) {
            int r = i >> 7, k = i & 127;
            At[i] = g_g1[(g0 + r) * 1024 + k0 + k];
        }
        for (int i = t; i < 128 * 32; i += 256) {
            int k = i >> 5, cc = i & 31;
            Wt[i] = Wf2[(k0 + k) * 128 + c0 + cc];
        }
        __syncthreads();
        for (int k = 0; k < 128; k++) {
            float wv = Wt[k * 32 + c];
#pragma unroll
            for (int j = 0; j < 8; j++)
                acc[j] += At[(rb + 8 * j) * 128 + k] * wv;
        }
        __syncthreads();
    }
    float bias = bf2[c0 + c];
#pragma unroll
    for (int j = 0; j < 8; j++)
        out[(g0 + rb + 8 * j) * 128 + c0 + c] = acc[j] + bias;
}

// ---------------- launch ----------------
static int smem_bytes(int KPAD, int CPAD) {
    return (64 * (KPAD + 2) + 56 * (CPAD + 8)) * 4;
}

extern "C" void kernel_launch(void* const* d_in, const int* in_sizes, int n_in,
                              void* d_out, int out_size) {
    const float* x     = (const float*)d_in[0];
    const int*   ei    = (const int*)d_in[1];
    const int*   batch = (const int*)d_in[2];
    const float* W1 = (const float*)d_in[3];
    const float* b1 = (const float*)d_in[4];
    const float* W2 = (const float*)d_in[5];
    const float* b2 = (const float*)d_in[6];
    const float* W3 = (const float*)d_in[7];
    const float* b3 = (const float*)d_in[8];
    const float* Wf1 = (const float*)d_in[9];
    const float* bf1 = (const float*)d_in[10];
    const float* Wf2 = (const float*)d_in[11];
    const float* bf2 = (const float*)d_in[12];
    float* out = (float*)d_out;

    float *Wp1, *bp1, *Wp2, *bp2, *Wp3, *bp3;
    __nv_bfloat16 *xpb, *h1b, *h2b, *h3b, *aggb;
    cudaGetSymbolAddress((void**)&xpb, g_xpb);
    cudaGetSymbolAddress((void**)&h1b, g_h1b);
    cudaGetSymbolAddress((void**)&h2b, g_h2b);
    cudaGetSymbolAddress((void**)&h3b, g_h3b);
    cudaGetSymbolAddress((void**)&aggb, g_aggb);
    cudaGetSymbolAddress((void**)&Wp1, g_Wp1);
    cudaGetSymbolAddress((void**)&bp1, g_bp1);
    cudaGetSymbolAddress((void**)&Wp2, g_Wp2);
    cudaGetSymbolAddress((void**)&bp2, g_bp2);
    cudaGetSymbolAddress((void**)&Wp3, g_Wp3);
    cudaGetSymbolAddress((void**)&bp3, g_bp3);

    cudaFuncSetAttribute(k_gemm_mma<56, 64, 64>,
                         cudaFuncAttributeMaxDynamicSharedMemorySize, smem_bytes(56, 64));
    cudaFuncSetAttribute(k_gemm_mma<56, 128, 64>,
                         cudaFuncAttributeMaxDynamicSharedMemorySize, smem_bytes(56, 128));
    cudaFuncSetAttribute(k_gemm_mma<112, 224, 112>,
                         cudaFuncAttributeMaxDynamicSharedMemorySize, smem_bytes(112, 224));
    int mlp1_smem = (64 * 216 + 216 * 32) * 4;
    cudaFuncSetAttribute(k_mlp1, cudaFuncAttributeMaxDynamicSharedMemorySize, mlp1_smem);

    k_zero<<<NBLK, 256>>>();
    k_merged<<<(M5 + 255) / 256, 256>>>(ei, batch, x, W1, b1, W2, b2, W3, b3);
    k_scan<<<NBLK, 256>>>();
    k_fill<<<(NT_EDGE + 255) / 256, 256>>>(ei);

    int ablk = (NN * 32 + 255) / 256;
    int gblk = (NN + 63) / 64;
    // layer 1: aggregate xpb -> aggb (bf16,64), GEMM 56 -> 64 + relu -> h1b
    k_agg64b<<<ablk, 256>>>(xpb, aggb);
    k_gemm_mma<56, 64, 64><<<gblk, 256, smem_bytes(56, 64)>>>(aggb, Wp1, bp1, h1b);
    // layer 2: aggregate h1b -> aggb (bf16,64), GEMM 56 -> 128 + relu -> h2b
    k_agg64b<<<ablk, 256>>>(h1b, aggb);
    k_gemm_mma<56, 128, 64><<<gblk, 256, smem_bytes(56, 128)>>>(aggb, Wp2, bp2, h2b);
    // layer 3: aggregate h2b -> aggb (bf16,112), GEMM 112 -> 224 + relu -> h3b
    k_agg128b<<<ablk, 256>>>(h2b, aggb);
    k_gemm_mma<112, 224, 112><<<gblk, 256, smem_bytes(112, 224)>>>(aggb, Wp3, bp3, h3b);

    k_pool<<<NG, 224>>>();
    k_mlp1<<<128, 256, mlp1_smem>>>(Wf1, bf1);
    k_mlp2<<<16, 256>>>(Wf2, bf2, out);
}

// round 14
// speedup vs baseline: 1.0412x; 1.0412x over previous
#include <cuda_runtime.h>
#include <cuda_bf16.h>

#define NN 100000
#define NE 1600000
#define NT_EDGE 1700000   // edges + self loops
#define NG 256
#define NBLK 391          // ceil(NN/256)

// ---------------- scratch (static device allocations; no runtime alloc) ----
__device__ int   g_cnt[NN];               // in-degree WITHOUT self loop
__device__ int   g_rank[NE];              // within-bucket rank of each edge
__device__ int   g_rowptr[NN + 1];
__device__ int   g_bsum[NBLK];
__device__ __align__(16) int2  g_edata[NT_EDGE];        // {src, f2i(norm)} by dst
__device__ __align__(256) __nv_bfloat16 g_xpb[NN * 64];  // x padded, bf16, stride 64 (1 line)
__device__ __align__(256) __nv_bfloat16 g_h1b[NN * 64];  // layer1 out bf16 (54 real)
__device__ __align__(256) __nv_bfloat16 g_h2b[NN * 128]; // layer2 out bf16 (108 real)
__device__ __align__(256) __nv_bfloat16 g_h3b[NN * 224]; // layer3 out bf16 (216 real)
__device__ __align__(256) __nv_bfloat16 g_aggb[NN * 112];// aggregation out bf16
__device__ __align__(16) float g_Wp1[56 * 64];
__device__ __align__(16) float g_Wp2[56 * 128];
__device__ __align__(16) float g_Wp3[112 * 224];
__device__ float g_bp1[64], g_bp2[128], g_bp3[224];
__device__ float g_pool[NG * 216];
__device__ int   g_goff[NG + 1];
__device__ float g_g1[NG * 1024];

// ---------------- zero pass (must precede merged atomics) ----------------
__global__ void k_zero() {
    int i = blockIdx.x * blockDim.x + threadIdx.x;
    if (i < NN) g_cnt[i] = 0;
}

// ---------------- merged preprocessing: counts(+rank) + boundaries + padW + xpad
#define PW1 (56 * 64 + 64)
#define PW2 (56 * 128 + 128)
#define PW3 (112 * 224 + 224)
#define M0 NE
#define M1 (M0 + NN)
#define M2 (M1 + PW1)
#define M3 (M2 + PW2)
#define M4 (M3 + PW3)
#define M5 (M4 + NN * 8)

__device__ __forceinline__ void padw_one(int j, const float* W, const float* b,
                                         float* Wp, float* bp, int K, int C,
                                         int KPAD, int CPAD) {
    int tot = KPAD * CPAD;
    if (j < tot) {
        int cc = j % CPAD, kk = j / CPAD;
        Wp[j] = (cc < C && kk < K) ? W[kk * C + cc] : 0.f;
    } else {
        int cc = j - tot;
        bp[cc] = (cc < C) ? b[cc] : 0.f;
    }
}

__global__ void k_merged(const int* __restrict__ ei, const int* __restrict__ batch,
                         const float* __restrict__ x,
                         const float* __restrict__ W1, const float* __restrict__ b1,
                         const float* __restrict__ W2, const float* __restrict__ b2,
                         const float* __restrict__ W3, const float* __restrict__ b3) {
    int i = blockIdx.x * blockDim.x + threadIdx.x;
    if (i < M0) {
        g_rank[i] = atomicAdd(&g_cnt[ei[NE + i]], 1);   // count AND capture rank
    } else if (i < M1) {
        int j = i - M0;
        int bi = batch[j];
        int bprev = (j > 0) ? batch[j - 1] : -1;
        for (int g = bprev + 1; g <= bi; g++) g_goff[g] = j;
        if (j == NN - 1)
            for (int g = bi + 1; g <= NG; g++) g_goff[g] = NN;
    } else if (i < M2) {
        padw_one(i - M1, W1, b1, g_Wp1, g_bp1, 54, 54, 56, 64);
    } else if (i < M3) {
        padw_one(i - M2, W2, b2, g_Wp2, g_bp2, 54, 108, 56, 128);
    } else if (i < M4) {
        padw_one(i - M3, W3, b3, g_Wp3, g_bp3, 108, 216, 112, 224);
    } else if (i < M5) {
        int j = i - M4;
        int r = j >> 3, cw = (j & 7) * 8;
        __nv_bfloat16 tmp[8];
#pragma unroll
        for (int t = 0; t < 8; t++) {
            int c = cw + t;
            tmp[t] = __float2bfloat16((c < 54) ? x[r * 54 + c] : 0.f);
        }
        *(uint4*)&g_xpb[r * 64 + cw] = *(uint4*)tmp;
    }
}

// ---------------- parallel scan of (cnt+1): block sums -> scan -> local ---
__global__ void k_s1() {            // grid NBLK, block 256
    int b = blockIdx.x, t = threadIdx.x;
    int i = b * 256 + t;
    int v = (i < NN) ? g_cnt[i] + 1 : 0;    // +1 self loop
#pragma unroll
    for (int off = 16; off > 0; off >>= 1)
        v += __shfl_down_sync(0xffffffffu, v, off);
    __shared__ int sm[8];
    if ((t & 31) == 0) sm[t >> 5] = v;
    __syncthreads();
    if (t == 0) {
        int s = 0;
#pragma unroll
        for (int j = 0; j < 8; j++) s += sm[j];
        g_bsum[b] = s;
    }
}

__global__ void k_s2() {            // 1 block, 512 threads: exclusive scan of g_bsum
    __shared__ int p[512];
    int t = threadIdx.x;
    int v = (t < NBLK) ? g_bsum[t] : 0;
    p[t] = v;
    __syncthreads();
    for (int off = 1; off < 512; off <<= 1) {
        int u = (t >= off) ? p[t - off] : 0;
        __syncthreads();
        p[t] += u;
        __syncthreads();
    }
    if (t < NBLK) g_bsum[t] = p[t] - v;   // exclusive
}

__global__ void k_s3() {            // grid NBLK, block 256: local scan + offset
    __shared__ int p[256];
    int b = blockIdx.x, t = threadIdx.x;
    int i = b * 256 + t;
    int v = (i < NN) ? g_cnt[i] + 1 : 0;    // +1 self loop
    p[t] = v;
    __syncthreads();
    for (int off = 1; off < 256; off <<= 1) {
        int u = (t >= off) ? p[t - off] : 0;
        __syncthreads();
        p[t] += u;
        __syncthreads();
    }
    int excl = p[t] - v + g_bsum[b];
    if (i < NN) g_rowptr[i] = excl;
    if (i == NN - 1) g_rowptr[NN] = excl + v;
}

// ---------------- fill (no atomics: rank precomputed) ----------------
__global__ void k_fill(const int* __restrict__ ei) {
    int i = blockIdx.x * blockDim.x + threadIdx.x;
    if (i >= NT_EDGE) return;
    int r, c, rk;
    if (i < NE) { r = ei[i]; c = ei[NE + i]; rk = g_rank[i]; }
    else        { r = c = i - NE; rk = g_cnt[c]; }   // self loop: last slot
    float nrm = rsqrtf((float)(g_cnt[r] + 1) * (float)(g_cnt[c] + 1));
    g_edata[g_rowptr[c] + rk] = make_int2(r, __float_as_int(nrm));
}

// ---------------- aggregation (bf16 gather, fp32 acc, bf16 out) -----------
__device__ __forceinline__ void acc8(float acc[8], float nrm, uint4 t) {
    float2 f0 = __bfloat1622float2(*(__nv_bfloat162*)&t.x);
    float2 f1 = __bfloat1622float2(*(__nv_bfloat162*)&t.y);
    float2 f2 = __bfloat1622float2(*(__nv_bfloat162*)&t.z);
    float2 f3 = __bfloat1622float2(*(__nv_bfloat162*)&t.w);
    acc[0] += nrm * f0.x; acc[1] += nrm * f0.y;
    acc[2] += nrm * f1.x; acc[3] += nrm * f1.y;
    acc[4] += nrm * f2.x; acc[5] += nrm * f2.y;
    acc[6] += nrm * f3.x; acc[7] += nrm * f3.y;
}

__device__ __forceinline__ uint4 pack8(const float acc[8]) {
    uint4 r;
    *(__nv_bfloat162*)&r.x = __float22bfloat162_rn(make_float2(acc[0], acc[1]));
    *(__nv_bfloat162*)&r.y = __float22bfloat162_rn(make_float2(acc[2], acc[3]));
    *(__nv_bfloat162*)&r.z = __float22bfloat162_rn(make_float2(acc[4], acc[5]));
    *(__nv_bfloat162*)&r.w = __float22bfloat162_rn(make_float2(acc[6], acc[7]));
    return r;
}

// 64-bf16 rows (128B = 1 line). 8 edges/warp-iter. bf16 out rows stride 64.
__global__ void k_agg64b(const __nv_bfloat16* __restrict__ in,
                         __nv_bfloat16* __restrict__ out) {
    int w = (blockIdx.x * blockDim.x + threadIdx.x) >> 5;
    int lane = threadIdx.x & 31;
    if (w >= NN) return;
    int q = lane >> 3, sl = lane & 7;
    int e0 = g_rowptr[w], e1 = g_rowptr[w + 1];
    float acc[8];
#pragma unroll
    for (int j = 0; j < 8; j++) acc[j] = 0.f;
    for (int e = e0; e < e1; e += 8) {
        int i0 = e + q, i1 = e + 4 + q;
        bool v0 = i0 < e1, v1 = i1 < e1;
        int2 ed0 = __ldg(&g_edata[v0 ? i0 : e]);
        int2 ed1 = __ldg(&g_edata[v1 ? i1 : e]);
        float n0 = v0 ? __int_as_float(ed0.y) : 0.f;
        float n1 = v1 ? __int_as_float(ed1.y) : 0.f;
        const uint4* s0 = (const uint4*)(in + (long)ed0.x * 64);
        const uint4* s1 = (const uint4*)(in + (long)ed1.x * 64);
        uint4 t0 = __ldg(&s0[sl]);
        uint4 t1 = __ldg(&s1[sl]);
        acc8(acc, n0, t0);
        acc8(acc, n1, t1);
    }
#pragma unroll
    for (int j = 0; j < 8; j++) {
        acc[j] += __shfl_xor_sync(0xffffffffu, acc[j], 8);
        acc[j] += __shfl_xor_sync(0xffffffffu, acc[j], 16);
    }
    if (q == 0)   // all 8 sl active: full 64-el row (cols 54-63 are zeros)
        ((uint4*)(out + (long)w * 64))[sl] = pack8(acc);
}

// 128-bf16 rows (256B = 2 lines). 4 edges/warp-iter. bf16 out rows stride 112.
__global__ void k_agg128b(const __nv_bfloat16* __restrict__ in,
                          __nv_bfloat16* __restrict__ out) {
    int w = (blockIdx.x * blockDim.x + threadIdx.x) >> 5;
    int lane = threadIdx.x & 31;
    if (w >= NN) return;
    int half = lane >> 4, sl = lane & 15;
    int e0 = g_rowptr[w], e1 = g_rowptr[w + 1];
    float acc[8];
#pragma unroll
    for (int j = 0; j < 8; j++) acc[j] = 0.f;
    for (int e = e0; e < e1; e += 4) {
        int i0 = e + half, i1 = e + 2 + half;
        bool v0 = i0 < e1, v1 = i1 < e1;
        int2 ed0 = __ldg(&g_edata[v0 ? i0 : e]);
        int2 ed1 = __ldg(&g_edata[v1 ? i1 : e]);
        float n0 = v0 ? __int_as_float(ed0.y) : 0.f;
        float n1 = v1 ? __int_as_float(ed1.y) : 0.f;
        const uint4* s0 = (const uint4*)(in + (long)ed0.x * 128);
        const uint4* s1 = (const uint4*)(in + (long)ed1.x * 128);
        uint4 t0 = __ldg(&s0[sl]);
        uint4 t1 = __ldg(&s1[sl]);
        acc8(acc, n0, t0);
        acc8(acc, n1, t1);
    }
#pragma unroll
    for (int j = 0; j < 8; j++)
        acc[j] += __shfl_xor_sync(0xffffffffu, acc[j], 16);
    if (half == 0 && sl < 14)   // 112-el row
        ((uint4*)(out + (long)w * 112))[sl] = pack8(acc);
}

// ---------------- tf32 tensor-core GEMM (A staged from bf16), bf16 out ----
__device__ __forceinline__ unsigned f2tf(float v) {
    unsigned u;
    asm("cvt.rna.tf32.f32 %0, %1;" : "=r"(u) : "f"(v));
    return u;
}

__device__ __forceinline__ void mma_tf32(float c[4], const unsigned a[4], const unsigned b[2]) {
    asm volatile(
        "mma.sync.aligned.m16n8k8.row.col.f32.tf32.tf32.f32 "
        "{%0,%1,%2,%3}, {%4,%5,%6,%7}, {%8,%9}, {%0,%1,%2,%3};\n"
        : "+f"(c[0]), "+f"(c[1]), "+f"(c[2]), "+f"(c[3])
        : "r"(a[0]), "r"(a[1]), "r"(a[2]), "r"(a[3]), "r"(b[0]), "r"(b[1]));
}

// A: bf16 rows of stride SRCSTR (>= KPAD), first KPAD cols used.
template <int KPAD, int CPAD, int SRCSTR>
__global__ __launch_bounds__(256)
void k_gemm_mma(const __nv_bfloat16* __restrict__ A, const float* __restrict__ W,
                const float* __restrict__ bias, __nv_bfloat16* __restrict__ out) {
    extern __shared__ float sm[];
    constexpr int ASTR = KPAD + 2;
    constexpr int WSTR = CPAD + 8;
    constexpr int KCH = 56;
    constexpr int NTILES = CPAD / 32;
    float* As = sm;                       // [64][ASTR]
    float* Ws = sm + 64 * ASTR;           // [KCH][WSTR]

    int tid = threadIdx.x;
    int w = tid >> 5, lane = tid & 31;
    int g = lane >> 2, ctg = lane & 3;
    int wm = w & 1, wn = w >> 1;
    int row0 = blockIdx.x * 64;

    float c[2][NTILES][4];
#pragma unroll
    for (int mt = 0; mt < 2; mt++)
#pragma unroll
        for (int nt = 0; nt < NTILES; nt++)
#pragma unroll
            for (int i = 0; i < 4; i++) c[mt][nt][i] = 0.f;

    // stage A: bf16 -> tf32 (KPAD % 8 == 0, 8 els per thread-chunk)
    for (int i = tid * 8; i < 64 * KPAD; i += 256 * 8) {
        int r = i / KPAD, k = i % KPAD;
        uint4 v = make_uint4(0u, 0u, 0u, 0u);
        if (row0 + r < NN) v = *(const uint4*)&A[(long)(row0 + r) * SRCSTR + k];
        const __nv_bfloat16* hb = (const __nv_bfloat16*)&v;
        float* o = As + r * ASTR + k;
#pragma unroll
        for (int t = 0; t < 8; t++)
            o[t] = __uint_as_float(f2tf(__bfloat162float(hb[t])));
    }

#pragma unroll 1
    for (int kc = 0; kc < KPAD; kc += KCH) {
        constexpr int kchunk = (KPAD < KCH) ? KPAD : KCH;
        for (int i = tid * 4; i < kchunk * CPAD; i += 256 * 4) {
            int kk = i / CPAD, cc = i % CPAD;
            float4 v = *(const float4*)&W[(long)(kc + kk) * CPAD + cc];
            float4 t;
            t.x = __uint_as_float(f2tf(v.x));
            t.y = __uint_as_float(f2tf(v.y));
            t.z = __uint_as_float(f2tf(v.z));
            t.w = __uint_as_float(f2tf(v.w));
            *(float4*)&Ws[kk * WSTR + cc] = t;
        }
        __syncthreads();

#pragma unroll
        for (int ks = 0; ks < kchunk; ks += 8) {
            unsigned a[2][4];
#pragma unroll
            for (int mt = 0; mt < 2; mt++) {
                int ar = wm * 32 + mt * 16;
                int kb = kc + ks + ctg;
                a[mt][0] = __float_as_uint(As[(ar + g) * ASTR + kb]);
                a[mt][1] = __float_as_uint(As[(ar + g + 8) * ASTR + kb]);
                a[mt][2] = __float_as_uint(As[(ar + g) * ASTR + kb + 4]);
                a[mt][3] = __float_as_uint(As[(ar + g + 8) * ASTR + kb + 4]);
            }
            unsigned b[NTILES][2];
#pragma unroll
            for (int nt = 0; nt < NTILES; nt++) {
                int col = wn * (CPAD / 4) + nt * 8 + g;
                b[nt][0] = __float_as_uint(Ws[(ks + ctg) * WSTR + col]);
                b[nt][1] = __float_as_uint(Ws[(ks + ctg + 4) * WSTR + col]);
            }
#pragma unroll
            for (int mt = 0; mt < 2; mt++)
#pragma unroll
                for (int nt = 0; nt < NTILES; nt++)
                    mma_tf32(c[mt][nt], a[mt], b[nt]);
        }
        __syncthreads();
    }

#pragma unroll
    for (int mt = 0; mt < 2; mt++) {
        int r0 = row0 + wm * 32 + mt * 16 + g;
#pragma unroll
        for (int nt = 0; nt < NTILES; nt++) {
            int col = wn * (CPAD / 4) + nt * 8 + 2 * ctg;
            float b0 = bias[col], b1 = bias[col + 1];
            if (r0 < NN)
                *(__nv_bfloat162*)&out[(long)r0 * CPAD + col] =
                    __float22bfloat162_rn(make_float2(
                        fmaxf(c[mt][nt][0] + b0, 0.f), fmaxf(c[mt][nt][1] + b1, 0.f)));
            if (r0 + 8 < NN)
                *(__nv_bfloat162*)&out[(long)(r0 + 8) * CPAD + col] =
                    __float22bfloat162_rn(make_float2(
                        fmaxf(c[mt][nt][2] + b0, 0.f), fmaxf(c[mt][nt][3] + b1, 0.f)));
        }
    }
}

// ---------------- pooling (bf16 in, fp32 accumulate) ----------------
__global__ void k_pool() {    // grid NG, block 224
    int g = blockIdx.x, f = threadIdx.x;
    if (f >= 216) return;
    int v0 = g_goff[g], v1 = g_goff[g + 1];
    float s = 0.f;
    for (int v = v0; v < v1; v++) s += __bfloat162float(g_h3b[(long)v * 224 + f]);
    float cnt = (float)(v1 - v0);
    g_pool[g * 216 + f] = s / fmaxf(cnt, 1.f);
}

// ---------------- tiled MLP head (fp32) ----------------
__global__ __launch_bounds__(256) void k_mlp1(const float* __restrict__ Wf1,
                                              const float* __restrict__ bf1) {
    extern __shared__ float smm[];
    float* Pt = smm;            // [64][216]
    float* Wt = smm + 64 * 216; // [216][32]
    int b = blockIdx.x, t = threadIdx.x;
    int bi = b >> 5, bj = b & 31;
    int g0 = bi * 64, c0 = bj * 32;
    for (int i = t; i < 64 * 216; i += 256) {
        int r = i / 216, k = i - r * 216;
        Pt[i] = g_pool[(g0 + r) * 216 + k];
    }
    for (int i = t; i < 216 * 32; i += 256) {
        int k = i >> 5, c = i & 31;
        Wt[i] = Wf1[k * 1024 + c0 + c];
    }
    __syncthreads();
    int c = t & 31, rb = t >> 5;
    float acc[8];
#pragma unroll
    for (int j = 0; j < 8; j++) acc[j] = 0.f;
    for (int k = 0; k < 216; k++) {
        float wv = Wt[k * 32 + c];
#pragma unroll
        for (int j = 0; j < 8; j++)
            acc[j] += Pt[(rb + 8 * j) * 216 + k] * wv;
    }
    float bias = bf1[c0 + c];
#pragma unroll
    for (int j = 0; j < 8; j++)
        g_g1[(g0 + rb + 8 * j) * 1024 + c0 + c] = fmaxf(acc[j] + bias, 0.f);
}

__global__ __launch_bounds__(256) void k_mlp2(const float* __restrict__ Wf2,
                                              const float* __restrict__ bf2,
                                              float* __restrict__ out) {
    __shared__ float At[64 * 128];   // 32KB
    __shared__ float Wt[128 * 32];   // 16KB
    int b = blockIdx.x, t = threadIdx.x;
    int bi = b >> 2, bj = b & 3;
    int g0 = bi * 64, c0 = bj * 32;
    int c = t & 31, rb = t >> 5;
    float acc[8];
#pragma unroll
    for (int j = 0; j < 8; j++) acc[j] = 0.f;
    for (int k0 = 0; k0 < 1024; k0 += 128) {
        for (int i = t; i < 64 * 128; i += 256) {
            int r = i >> 7, k = i & 127;
            At[i] = g_g1[(g0 + r) * 1024 + k0 + k];
        }
        for (int i = t; i < 128 * 32; i += 256) {
            int k = i >> 5, cc = i & 31;
            Wt[i] = Wf2[(k0 + k) * 128 + c0 + cc];
        }
        __syncthreads();
        for (int k = 0; k < 128; k++) {
            float wv = Wt[k * 32 + c];
#pragma unroll
            for (int j = 0; j < 8; j++)
                acc[j] += At[(rb + 8 * j) * 128 + k] * wv;
        }
        __syncthreads();
    }
    float bias = bf2[c0 + c];
#pragma unroll
    for (int j = 0; j < 8; j++)
        out[(g0 + rb + 8 * j) * 128 + c0 + c] = acc[j] + bias;
}

// ---------------- launch ----------------
static int smem_bytes(int KPAD, int CPAD) {
    return (64 * (KPAD + 2) + 56 * (CPAD + 8)) * 4;
}

extern "C" void kernel_launch(void* const* d_in, const int* in_sizes, int n_in,
                              void* d_out, int out_size) {
    const float* x     = (const float*)d_in[0];
    const int*   ei    = (const int*)d_in[1];
    const int*   batch = (const int*)d_in[2];
    const float* W1 = (const float*)d_in[3];
    const float* b1 = (const float*)d_in[4];
    const float* W2 = (const float*)d_in[5];
    const float* b2 = (const float*)d_in[6];
    const float* W3 = (const float*)d_in[7];
    const float* b3 = (const float*)d_in[8];
    const float* Wf1 = (const float*)d_in[9];
    const float* bf1 = (const float*)d_in[10];
    const float* Wf2 = (const float*)d_in[11];
    const float* bf2 = (const float*)d_in[12];
    float* out = (float*)d_out;

    float *Wp1, *bp1, *Wp2, *bp2, *Wp3, *bp3;
    __nv_bfloat16 *xpb, *h1b, *h2b, *h3b, *aggb;
    cudaGetSymbolAddress((void**)&xpb, g_xpb);
    cudaGetSymbolAddress((void**)&h1b, g_h1b);
    cudaGetSymbolAddress((void**)&h2b, g_h2b);
    cudaGetSymbolAddress((void**)&h3b, g_h3b);
    cudaGetSymbolAddress((void**)&aggb, g_aggb);
    cudaGetSymbolAddress((void**)&Wp1, g_Wp1);
    cudaGetSymbolAddress((void**)&bp1, g_bp1);
    cudaGetSymbolAddress((void**)&Wp2, g_Wp2);
    cudaGetSymbolAddress((void**)&bp2, g_bp2);
    cudaGetSymbolAddress((void**)&Wp3, g_Wp3);
    cudaGetSymbolAddress((void**)&bp3, g_bp3);

    cudaFuncSetAttribute(k_gemm_mma<56, 64, 64>,
                         cudaFuncAttributeMaxDynamicSharedMemorySize, smem_bytes(56, 64));
    cudaFuncSetAttribute(k_gemm_mma<56, 128, 64>,
                         cudaFuncAttributeMaxDynamicSharedMemorySize, smem_bytes(56, 128));
    cudaFuncSetAttribute(k_gemm_mma<112, 224, 112>,
                         cudaFuncAttributeMaxDynamicSharedMemorySize, smem_bytes(112, 224));
    int mlp1_smem = (64 * 216 + 216 * 32) * 4;
    cudaFuncSetAttribute(k_mlp1, cudaFuncAttributeMaxDynamicSharedMemorySize, mlp1_smem);

    k_zero<<<NBLK, 256>>>();
    k_merged<<<(M5 + 255) / 256, 256>>>(ei, batch, x, W1, b1, W2, b2, W3, b3);
    k_s1<<<NBLK, 256>>>();
    k_s2<<<1, 512>>>();
    k_s3<<<NBLK, 256>>>();
    k_fill<<<(NT_EDGE + 255) / 256, 256>>>(ei);

    int ablk = (NN * 32 + 255) / 256;
    int gblk = (NN + 63) / 64;
    // layer 1: aggregate xpb -> aggb (bf16,64), GEMM 56 -> 64 + relu -> h1b
    k_agg64b<<<ablk, 256>>>(xpb, aggb);
    k_gemm_mma<56, 64, 64><<<gblk, 256, smem_bytes(56, 64)>>>(aggb, Wp1, bp1, h1b);
    // layer 2: aggregate h1b -> aggb (bf16,64), GEMM 56 -> 128 + relu -> h2b
    k_agg64b<<<ablk, 256>>>(h1b, aggb);
    k_gemm_mma<56, 128, 64><<<gblk, 256, smem_bytes(56, 128)>>>(aggb, Wp2, bp2, h2b);
    // layer 3: aggregate h2b -> aggb (bf16,112), GEMM 112 -> 224 + relu -> h3b
    k_agg128b<<<ablk, 256>>>(h2b, aggb);
    k_gemm_mma<112, 224, 112><<<gblk, 256, smem_bytes(112, 224)>>>(aggb, Wp3, bp3, h3b);

    k_pool<<<NG, 224>>>();
    k_mlp1<<<128, 256, mlp1_smem>>>(Wf1, bf1);
    k_mlp2<<<16, 256>>>(Wf2, bf2, out);
}

// round 15
// speedup vs baseline: 1.1486x; 1.1031x over previous
#include <cuda_runtime.h>
#include <cuda_bf16.h>

#define NN 100000
#define NE 1600000
#define NT_EDGE 1700000   // edges + self loops
#define NG 256
#define NBLK 391          // ceil(NN/256)

// ---------------- scratch (static device allocations; no runtime alloc) ----
__device__ int   g_cnt[NN];               // in-degree WITHOUT self loop
__device__ int   g_fill[NN];
__device__ int   g_rowptr[NN + 1];
__device__ int   g_bsum[NBLK];
__device__ __align__(16) int2  g_edata[NT_EDGE];        // {src, f2i(norm)} by dst
__device__ __align__(256) __nv_bfloat16 g_xpb[NN * 64];  // x padded, bf16, stride 64 (1 line)
__device__ __align__(256) __nv_bfloat16 g_h1b[NN * 64];  // layer1 out bf16 (54 real)
__device__ __align__(256) __nv_bfloat16 g_h2b[NN * 128]; // layer2 out bf16 (108 real)
__device__ __align__(256) __nv_bfloat16 g_h3b[NN * 224]; // layer3 out bf16 (216 real)
__device__ __align__(256) __nv_bfloat16 g_aggb[NN * 112];// aggregation out bf16
// weights: bf16, TRANSPOSED [n][k] (k contiguous) for mma.m16n8k16 B frags
__device__ __align__(16) __nv_bfloat16 g_Wt1[64 * 64];
__device__ __align__(16) __nv_bfloat16 g_Wt2[128 * 64];
__device__ __align__(16) __nv_bfloat16 g_Wt3[224 * 112];
__device__ float g_bp1[64], g_bp2[128], g_bp3[224];
__device__ float g_pool[NG * 216];
__device__ int   g_goff[NG + 1];
__device__ float g_g1[NG * 1024];

// ---------------- zero pass (must precede merged atomics) ----------------
__global__ void k_zero() {
    int i = blockIdx.x * blockDim.x + threadIdx.x;
    if (i < NN) { g_cnt[i] = 0; g_fill[i] = 0; }
}

// ---------------- merged preprocessing: counts + boundaries + padW(T) + xpad
#define PW1 (64 * 64 + 64)
#define PW2 (128 * 64 + 128)
#define PW3 (224 * 112 + 224)
#define M0 NE
#define M1 (M0 + NN)
#define M2 (M1 + PW1)
#define M3 (M2 + PW2)
#define M4 (M3 + PW3)
#define M5 (M4 + NN * 8)

// transposed bf16 weight pad: Wt[cc][kk] = W[kk][cc], zero outside K x C
__device__ __forceinline__ void padw_t(int j, const float* W, const float* b,
                                       __nv_bfloat16* Wt, float* bp, int K, int C,
                                       int KPAD, int CPAD) {
    int tot = CPAD * KPAD;
    if (j < tot) {
        int cc = j / KPAD, kk = j - cc * KPAD;
        Wt[j] = __float2bfloat16((cc < C && kk < K) ? W[kk * C + cc] : 0.f);
    } else {
        int cc = j - tot;
        bp[cc] = (cc < C) ? b[cc] : 0.f;
    }
}

__global__ void k_merged(const int* __restrict__ ei, const int* __restrict__ batch,
                         const float* __restrict__ x,
                         const float* __restrict__ W1, const float* __restrict__ b1,
                         const float* __restrict__ W2, const float* __restrict__ b2,
                         const float* __restrict__ W3, const float* __restrict__ b3) {
    int i = blockIdx.x * blockDim.x + threadIdx.x;
    if (i < M0) {
        atomicAdd(&g_cnt[ei[NE + i]], 1);
    } else if (i < M1) {
        int j = i - M0;
        int bi = batch[j];
        int bprev = (j > 0) ? batch[j - 1] : -1;
        for (int g = bprev + 1; g <= bi; g++) g_goff[g] = j;
        if (j == NN - 1)
            for (int g = bi + 1; g <= NG; g++) g_goff[g] = NN;
    } else if (i < M2) {
        padw_t(i - M1, W1, b1, g_Wt1, g_bp1, 54, 54, 64, 64);
    } else if (i < M3) {
        padw_t(i - M2, W2, b2, g_Wt2, g_bp2, 54, 108, 64, 128);
    } else if (i < M4) {
        padw_t(i - M3, W3, b3, g_Wt3, g_bp3, 108, 216, 112, 224);
    } else if (i < M5) {
        int j = i - M4;
        int r = j >> 3, cw = (j & 7) * 8;
        __nv_bfloat16 tmp[8];
#pragma unroll
        for (int t = 0; t < 8; t++) {
            int c = cw + t;
            tmp[t] = __float2bfloat16((c < 54) ? x[r * 54 + c] : 0.f);
        }
        *(uint4*)&g_xpb[r * 64 + cw] = *(uint4*)tmp;
    }
}

// ---------------- parallel scan of (cnt+1): block sums -> scan -> local ---
__global__ void k_s1() {            // grid NBLK, block 256
    int b = blockIdx.x, t = threadIdx.x;
    int i = b * 256 + t;
    int v = (i < NN) ? g_cnt[i] + 1 : 0;    // +1 self loop
#pragma unroll
    for (int off = 16; off > 0; off >>= 1)
        v += __shfl_down_sync(0xffffffffu, v, off);
    __shared__ int sm[8];
    if ((t & 31) == 0) sm[t >> 5] = v;
    __syncthreads();
    if (t == 0) {
        int s = 0;
#pragma unroll
        for (int j = 0; j < 8; j++) s += sm[j];
        g_bsum[b] = s;
    }
}

__global__ void k_s2() {            // 1 block, 512 threads: exclusive scan of g_bsum
    __shared__ int p[512];
    int t = threadIdx.x;
    int v = (t < NBLK) ? g_bsum[t] : 0;
    p[t] = v;
    __syncthreads();
    for (int off = 1; off < 512; off <<= 1) {
        int u = (t >= off) ? p[t - off] : 0;
        __syncthreads();
        p[t] += u;
        __syncthreads();
    }
    if (t < NBLK) g_bsum[t] = p[t] - v;   // exclusive
}

__global__ void k_s3() {            // grid NBLK, block 256: local scan + offset
    __shared__ int p[256];
    int b = blockIdx.x, t = threadIdx.x;
    int i = b * 256 + t;
    int v = (i < NN) ? g_cnt[i] + 1 : 0;    // +1 self loop
    p[t] = v;
    __syncthreads();
    for (int off = 1; off < 256; off <<= 1) {
        int u = (t >= off) ? p[t - off] : 0;
        __syncthreads();
        p[t] += u;
        __syncthreads();
    }
    int excl = p[t] - v + g_bsum[b];
    if (i < NN) g_rowptr[i] = excl;
    if (i == NN - 1) g_rowptr[NN] = excl + v;
}

__global__ void k_fill(const int* __restrict__ ei) {
    int i = blockIdx.x * blockDim.x + threadIdx.x;
    if (i >= NT_EDGE) return;
    int r, c;
    if (i < NE) { r = ei[i]; c = ei[NE + i]; }
    else        { r = c = i - NE; }
    float nrm = rsqrtf((float)(g_cnt[r] + 1) * (float)(g_cnt[c] + 1));
    int pos = g_rowptr[c] + atomicAdd(&g_fill[c], 1);
    g_edata[pos] = make_int2(r, __float_as_int(nrm));
}

// ---------------- aggregation (bf16 gather, fp32 acc, bf16 out) -----------
__device__ __forceinline__ void acc8(float acc[8], float nrm, uint4 t) {
    float2 f0 = __bfloat1622float2(*(__nv_bfloat162*)&t.x);
    float2 f1 = __bfloat1622float2(*(__nv_bfloat162*)&t.y);
    float2 f2 = __bfloat1622float2(*(__nv_bfloat162*)&t.z);
    float2 f3 = __bfloat1622float2(*(__nv_bfloat162*)&t.w);
    acc[0] += nrm * f0.x; acc[1] += nrm * f0.y;
    acc[2] += nrm * f1.x; acc[3] += nrm * f1.y;
    acc[4] += nrm * f2.x; acc[5] += nrm * f2.y;
    acc[6] += nrm * f3.x; acc[7] += nrm * f3.y;
}

__device__ __forceinline__ uint4 pack8(const float acc[8]) {
    uint4 r;
    *(__nv_bfloat162*)&r.x = __float22bfloat162_rn(make_float2(acc[0], acc[1]));
    *(__nv_bfloat162*)&r.y = __float22bfloat162_rn(make_float2(acc[2], acc[3]));
    *(__nv_bfloat162*)&r.z = __float22bfloat162_rn(make_float2(acc[4], acc[5]));
    *(__nv_bfloat162*)&r.w = __float22bfloat162_rn(make_float2(acc[6], acc[7]));
    return r;
}

// 64-bf16 rows (128B = 1 line). 8 edges/warp-iter. bf16 out rows stride 64.
__global__ void k_agg64b(const __nv_bfloat16* __restrict__ in,
                         __nv_bfloat16* __restrict__ out) {
    int w = (blockIdx.x * blockDim.x + threadIdx.x) >> 5;
    int lane = threadIdx.x & 31;
    if (w >= NN) return;
    int q = lane >> 3, sl = lane & 7;
    int e0 = g_rowptr[w], e1 = g_rowptr[w + 1];
    float acc[8];
#pragma unroll
    for (int j = 0; j < 8; j++) acc[j] = 0.f;
    for (int e = e0; e < e1; e += 8) {
        int i0 = e + q, i1 = e + 4 + q;
        bool v0 = i0 < e1, v1 = i1 < e1;
        int2 ed0 = __ldg(&g_edata[v0 ? i0 : e]);
        int2 ed1 = __ldg(&g_edata[v1 ? i1 : e]);
        float n0 = v0 ? __int_as_float(ed0.y) : 0.f;
        float n1 = v1 ? __int_as_float(ed1.y) : 0.f;
        const uint4* s0 = (const uint4*)(in + (long)ed0.x * 64);
        const uint4* s1 = (const uint4*)(in + (long)ed1.x * 64);
        uint4 t0 = __ldg(&s0[sl]);
        uint4 t1 = __ldg(&s1[sl]);
        acc8(acc, n0, t0);
        acc8(acc, n1, t1);
    }
#pragma unroll
    for (int j = 0; j < 8; j++) {
        acc[j] += __shfl_xor_sync(0xffffffffu, acc[j], 8);
        acc[j] += __shfl_xor_sync(0xffffffffu, acc[j], 16);
    }
    if (q == 0)   // all 8 sl active: full 64-el row (cols 54-63 are zeros)
        ((uint4*)(out + (long)w * 64))[sl] = pack8(acc);
}

// 128-bf16 rows (256B = 2 lines). 4 edges/warp-iter. bf16 out rows stride 112.
__global__ void k_agg128b(const __nv_bfloat16* __restrict__ in,
                          __nv_bfloat16* __restrict__ out) {
    int w = (blockIdx.x * blockDim.x + threadIdx.x) >> 5;
    int lane = threadIdx.x & 31;
    if (w >= NN) return;
    int half = lane >> 4, sl = lane & 15;
    int e0 = g_rowptr[w], e1 = g_rowptr[w + 1];
    float acc[8];
#pragma unroll
    for (int j = 0; j < 8; j++) acc[j] = 0.f;
    for (int e = e0; e < e1; e += 4) {
        int i0 = e + half, i1 = e + 2 + half;
        bool v0 = i0 < e1, v1 = i1 < e1;
        int2 ed0 = __ldg(&g_edata[v0 ? i0 : e]);
        int2 ed1 = __ldg(&g_edata[v1 ? i1 : e]);
        float n0 = v0 ? __int_as_float(ed0.y) : 0.f;
        float n1 = v1 ? __int_as_float(ed1.y) : 0.f;
        const uint4* s0 = (const uint4*)(in + (long)ed0.x * 128);
        const uint4* s1 = (const uint4*)(in + (long)ed1.x * 128);
        uint4 t0 = __ldg(&s0[sl]);
        uint4 t1 = __ldg(&s1[sl]);
        acc8(acc, n0, t0);
        acc8(acc, n1, t1);
    }
#pragma unroll
    for (int j = 0; j < 8; j++)
        acc[j] += __shfl_xor_sync(0xffffffffu, acc[j], 16);
    if (half == 0 && sl < 14)   // 112-el row
        ((uint4*)(out + (long)w * 112))[sl] = pack8(acc);
}

// ---------------- bf16 tensor-core GEMM (m16n8k16), bf16 in/out ----------
__device__ __forceinline__ void mma_bf16(float c[4], const unsigned a[4], const unsigned b[2]) {
    asm volatile(
        "mma.sync.aligned.m16n8k16.row.col.f32.bf16.bf16.f32 "
        "{%0,%1,%2,%3}, {%4,%5,%6,%7}, {%8,%9}, {%0,%1,%2,%3};\n"
        : "+f"(c[0]), "+f"(c[1]), "+f"(c[2]), "+f"(c[3])
        : "r"(a[0]), "r"(a[1]), "r"(a[2]), "r"(a[3]), "r"(b[0]), "r"(b[1]));
}

// A: bf16 rows, contiguous stride == KPAD (64 or 112). Wt: bf16 [CPAD][KPAD].
// Block: 256 thr = 8 warps (2 M x 4 N); tile 64 x CPAD; warp 32 x CPAD/4.
template <int KPAD, int CPAD>
__global__ __launch_bounds__(256)
void k_gemm_bf16(const __nv_bfloat16* __restrict__ A, const __nv_bfloat16* __restrict__ Wt,
                 const float* __restrict__ bias, __nv_bfloat16* __restrict__ out) {
    extern __shared__ __nv_bfloat16 smh[];
    constexpr int ASTR = KPAD + 8;        // row strides: bank-conflict-free frags
    constexpr int NTILES = CPAD / 32;
    __nv_bfloat16* As = smh;              // [64][ASTR]
    __nv_bfloat16* Ws = smh + 64 * ASTR;  // [CPAD][ASTR]

    int tid = threadIdx.x;
    int w = tid >> 5, lane = tid & 31;
    int g = lane >> 2, ctg = lane & 3;
    int wm = w & 1, wn = w >> 1;
    int row0 = blockIdx.x * 64;

    // stage A (raw bf16 copy, rows contiguous)
    for (int i = tid * 8; i < 64 * KPAD; i += 256 * 8) {
        int r = i / KPAD, k = i - (i / KPAD) * KPAD;
        uint4 v = make_uint4(0u, 0u, 0u, 0u);
        if (row0 + r < NN) v = *(const uint4*)&A[(long)(row0 + r) * KPAD + k];
        *(uint4*)&As[r * ASTR + k] = v;
    }
    // stage Wt
    for (int i = tid * 8; i < CPAD * KPAD; i += 256 * 8) {
        int n = i / KPAD, k = i - (i / KPAD) * KPAD;
        *(uint4*)&Ws[n * ASTR + k] = *(const uint4*)&Wt[n * KPAD + k];
    }
    __syncthreads();

    float c[2][NTILES][4];
#pragma unroll
    for (int mt = 0; mt < 2; mt++)
#pragma unroll
        for (int nt = 0; nt < NTILES; nt++)
#pragma unroll
            for (int i = 0; i < 4; i++) c[mt][nt][i] = 0.f;

#pragma unroll
    for (int ks = 0; ks < KPAD; ks += 16) {
        unsigned a[2][4];
#pragma unroll
        for (int mt = 0; mt < 2; mt++) {
            int ar = wm * 32 + mt * 16;
            int kb = ks + 2 * ctg;
            a[mt][0] = *(const unsigned*)&As[(ar + g) * ASTR + kb];
            a[mt][1] = *(const unsigned*)&As[(ar + g + 8) * ASTR + kb];
            a[mt][2] = *(const unsigned*)&As[(ar + g) * ASTR + kb + 8];
            a[mt][3] = *(const unsigned*)&As[(ar + g + 8) * ASTR + kb + 8];
        }
        unsigned b[NTILES][2];
#pragma unroll
        for (int nt = 0; nt < NTILES; nt++) {
            int col = wn * (CPAD / 4) + nt * 8 + g;
            int kb = ks + 2 * ctg;
            b[nt][0] = *(const unsigned*)&Ws[col * ASTR + kb];
            b[nt][1] = *(const unsigned*)&Ws[col * ASTR + kb + 8];
        }
#pragma unroll
        for (int mt = 0; mt < 2; mt++)
#pragma unroll
            for (int nt = 0; nt < NTILES; nt++)
                mma_bf16(c[mt][nt], a[mt], b[nt]);
    }

#pragma unroll
    for (int mt = 0; mt < 2; mt++) {
        int r0 = row0 + wm * 32 + mt * 16 + g;
#pragma unroll
        for (int nt = 0; nt < NTILES; nt++) {
            int col = wn * (CPAD / 4) + nt * 8 + 2 * ctg;
            float b0 = bias[col], b1 = bias[col + 1];
            if (r0 < NN)
                *(__nv_bfloat162*)&out[(long)r0 * CPAD + col] =
                    __float22bfloat162_rn(make_float2(
                        fmaxf(c[mt][nt][0] + b0, 0.f), fmaxf(c[mt][nt][1] + b1, 0.f)));
            if (r0 + 8 < NN)
                *(__nv_bfloat162*)&out[(long)(r0 + 8) * CPAD + col] =
                    __float22bfloat162_rn(make_float2(
                        fmaxf(c[mt][nt][2] + b0, 0.f), fmaxf(c[mt][nt][3] + b1, 0.f)));
        }
    }
}

// ---------------- pooling (bf16 in, fp32 accumulate) ----------------
__global__ void k_pool() {    // grid NG, block 224
    int g = blockIdx.x, f = threadIdx.x;
    if (f >= 216) return;
    int v0 = g_goff[g], v1 = g_goff[g + 1];
    float s = 0.f;
    for (int v = v0; v < v1; v++) s += __bfloat162float(g_h3b[(long)v * 224 + f]);
    float cnt = (float)(v1 - v0);
    g_pool[g * 216 + f] = s / fmaxf(cnt, 1.f);
}

// ---------------- tiled MLP head (fp32) ----------------
__global__ __launch_bounds__(256) void k_mlp1(const float* __restrict__ Wf1,
                                              const float* __restrict__ bf1) {
    extern __shared__ float smm[];
    float* Pt = smm;            // [64][216]
    float* Wt = smm + 64 * 216; // [216][32]
    int b = blockIdx.x, t = threadIdx.x;
    int bi = b >> 5, bj = b & 31;
    int g0 = bi * 64, c0 = bj * 32;
    for (int i = t; i < 64 * 216; i += 256) {
        int r = i / 216, k = i - r * 216;
        Pt[i] = g_pool[(g0 + r) * 216 + k];
    }
    for (int i = t; i < 216 * 32; i += 256) {
        int k = i >> 5, c = i & 31;
        Wt[i] = Wf1[k * 1024 + c0 + c];
    }
    __syncthreads();
    int c = t & 31, rb = t >> 5;
    float acc[8];
#pragma unroll
    for (int j = 0; j < 8; j++) acc[j] = 0.f;
    for (int k = 0; k < 216; k++) {
        float wv = Wt[k * 32 + c];
#pragma unroll
        for (int j = 0; j < 8; j++)
            acc[j] += Pt[(rb + 8 * j) * 216 + k] * wv;
    }
    float bias = bf1[c0 + c];
#pragma unroll
    for (int j = 0; j < 8; j++)
        g_g1[(g0 + rb + 8 * j) * 1024 + c0 + c] = fmaxf(acc[j] + bias, 0.f);
}

__global__ __launch_bounds__(256) void k_mlp2(const float* __restrict__ Wf2,
                                              const float* __restrict__ bf2,
                                              float* __restrict__ out) {
    __shared__ float At[64 * 128];   // 32KB
    __shared__ float Wt[128 * 32];   // 16KB
    int b = blockIdx.x, t = threadIdx.x;
    int bi = b >> 2, bj = b & 3;
    int g0 = bi * 64, c0 = bj * 32;
    int c = t & 31, rb = t >> 5;
    float acc[8];
#pragma unroll
    for (int j = 0; j < 8; j++) acc[j] = 0.f;
    for (int k0 = 0; k0 < 1024; k0 += 128) {
        for (int i = t; i < 64 * 128; i += 256) {
            int r = i >> 7, k = i & 127;
            At[i] = g_g1[(g0 + r) * 1024 + k0 + k];
        }
        for (int i = t; i < 128 * 32; i += 256) {
            int k = i >> 5, cc = i & 31;
            Wt[i] = Wf2[(k0 + k) * 128 + c0 + cc];
        }
        __syncthreads();
        for (int k = 0; k < 128; k++) {
            float wv = Wt[k * 32 + c];
#pragma unroll
            for (int j = 0; j < 8; j++)
                acc[j] += At[(rb + 8 * j) * 128 + k] * wv;
        }
        __syncthreads();
    }
    float bias = bf2[c0 + c];
#pragma unroll
    for (int j = 0; j < 8; j++)
        out[(g0 + rb + 8 * j) * 128 + c0 + c] = acc[j] + bias;
}

// ---------------- launch ----------------
static int smem_bytes_bf16(int KPAD, int CPAD) {
    return (64 + CPAD) * (KPAD + 8) * 2;
}

extern "C" void kernel_launch(void* const* d_in, const int* in_sizes, int n_in,
                              void* d_out, int out_size) {
    const float* x     = (const float*)d_in[0];
    const int*   ei    = (const int*)d_in[1];
    const int*   batch = (const int*)d_in[2];
    const float* W1 = (const float*)d_in[3];
    const float* b1 = (const float*)d_in[4];
    const float* W2 = (const float*)d_in[5];
    const float* b2 = (const float*)d_in[6];
    const float* W3 = (const float*)d_in[7];
    const float* b3 = (const float*)d_in[8];
    const float* Wf1 = (const float*)d_in[9];
    const float* bf1 = (const float*)d_in[10];
    const float* Wf2 = (const float*)d_in[11];
    const float* bf2 = (const float*)d_in[12];
    float* out = (float*)d_out;

    float *bp1, *bp2, *bp3;
    __nv_bfloat16 *xpb, *h1b, *h2b, *h3b, *aggb, *Wt1, *Wt2, *Wt3;
    cudaGetSymbolAddress((void**)&xpb, g_xpb);
    cudaGetSymbolAddress((void**)&h1b, g_h1b);
    cudaGetSymbolAddress((void**)&h2b, g_h2b);
    cudaGetSymbolAddress((void**)&h3b, g_h3b);
    cudaGetSymbolAddress((void**)&aggb, g_aggb);
    cudaGetSymbolAddress((void**)&Wt1, g_Wt1);
    cudaGetSymbolAddress((void**)&Wt2, g_Wt2);
    cudaGetSymbolAddress((void**)&Wt3, g_Wt3);
    cudaGetSymbolAddress((void**)&bp1, g_bp1);
    cudaGetSymbolAddress((void**)&bp2, g_bp2);
    cudaGetSymbolAddress((void**)&bp3, g_bp3);

    cudaFuncSetAttribute(k_gemm_bf16<64, 64>,
                         cudaFuncAttributeMaxDynamicSharedMemorySize, smem_bytes_bf16(64, 64));
    cudaFuncSetAttribute(k_gemm_bf16<64, 128>,
                         cudaFuncAttributeMaxDynamicSharedMemorySize, smem_bytes_bf16(64, 128));
    cudaFuncSetAttribute(k_gemm_bf16<112, 224>,
                         cudaFuncAttributeMaxDynamicSharedMemorySize, smem_bytes_bf16(112, 224));
    int mlp1_smem = (64 * 216 + 216 * 32) * 4;
    cudaFuncSetAttribute(k_mlp1, cudaFuncAttributeMaxDynamicSharedMemorySize, mlp1_smem);

    k_zero<<<NBLK, 256>>>();
    k_merged<<<(M5 + 255) / 256, 256>>>(ei, batch, x, W1, b1, W2, b2, W3, b3);
    k_s1<<<NBLK, 256>>>();
    k_s2<<<1, 512>>>();
    k_s3<<<NBLK, 256>>>();
    k_fill<<<(NT_EDGE + 255) / 256, 256>>>(ei);

    int ablk = (NN * 32 + 255) / 256;
    int gblk = (NN + 63) / 64;
    // layer 1: aggregate xpb -> aggb (bf16,64), bf16 GEMM K=64 -> 64 + relu -> h1b
    k_agg64b<<<ablk, 256>>>(xpb, aggb);
    k_gemm_bf16<64, 64><<<gblk, 256, smem_bytes_bf16(64, 64)>>>(aggb, Wt1, bp1, h1b);
    // layer 2: aggregate h1b -> aggb (bf16,64), bf16 GEMM K=64 -> 128 + relu -> h2b
    k_agg64b<<<ablk, 256>>>(h1b, aggb);
    k_gemm_bf16<64, 128><<<gblk, 256, smem_bytes_bf16(64, 128)>>>(aggb, Wt2, bp2, h2b);
    // layer 3: aggregate h2b -> aggb (bf16,112), bf16 GEMM K=112 -> 224 + relu -> h3b
    k_agg128b<<<ablk, 256>>>(h2b, aggb);
    k_gemm_bf16<112, 224><<<gblk, 256, smem_bytes_bf16(112, 224)>>>(aggb, Wt3, bp3, h3b);

    k_pool<<<NG, 224>>>();
    k_mlp1<<<128, 256, mlp1_smem>>>(Wf1, bf1);
    k_mlp2<<<16, 256>>>(Wf2, bf2, out);
}

// round 16
// speedup vs baseline: 1.1729x; 1.0212x over previous
#include <cuda_runtime.h>
#include <cuda_bf16.h>

#define NN 100000
#define NE 1600000
#define NT_EDGE 1700000   // edges + self loops
#define NG 256
#define NBLK 391          // ceil(NN/256)

// ---------------- scratch (static device allocations; no runtime alloc) ----
__device__ int   g_cnt[NN];               // in-degree WITHOUT self loop
__device__ int   g_fill[NN];
__device__ int   g_rowptr[NN];            // segment base per node (unordered alloc)
__device__ int   g_total;
__device__ __align__(16) int2  g_edata[NT_EDGE];        // {src, f2i(norm)} by dst
__device__ __align__(256) __nv_bfloat16 g_xpb[NN * 64];  // x padded, bf16, stride 64 (1 line)
__device__ __align__(256) __nv_bfloat16 g_h1b[NN * 64];  // layer1 out bf16 (54 real)
__device__ __align__(256) __nv_bfloat16 g_h2b[NN * 128]; // layer2 out bf16 (108 real)
__device__ __align__(256) __nv_bfloat16 g_h3b[NN * 224]; // layer3 out bf16 (216 real)
__device__ __align__(256) __nv_bfloat16 g_aggb[NN * 112];// aggregation out bf16
// weights: bf16, TRANSPOSED [n][k] (k contiguous) for mma.m16n8k16 B frags
__device__ __align__(16) __nv_bfloat16 g_Wt1[64 * 64];
__device__ __align__(16) __nv_bfloat16 g_Wt2[128 * 64];
__device__ __align__(16) __nv_bfloat16 g_Wt3[224 * 112];
__device__ float g_bp1[64], g_bp2[128], g_bp3[224];
__device__ float g_pool[NG * 216];
__device__ int   g_goff[NG + 1];
__device__ float g_g1[NG * 1024];

// ---------------- zero pass (must precede merged atomics) ----------------
__global__ void k_zero() {
    int i = blockIdx.x * blockDim.x + threadIdx.x;
    if (i < NN) g_cnt[i] = 0;
    if (i == 0) g_total = 0;
}

// ---------------- merged preprocessing: counts + boundaries + padW(T) + xpad
#define PW1 (64 * 64 + 64)
#define PW2 (128 * 64 + 128)
#define PW3 (224 * 112 + 224)
#define M0 NE
#define M1 (M0 + NN)
#define M2 (M1 + PW1)
#define M3 (M2 + PW2)
#define M4 (M3 + PW3)
#define M5 (M4 + NN * 8)

// transposed bf16 weight pad: Wt[cc][kk] = W[kk][cc], zero outside K x C
__device__ __forceinline__ void padw_t(int j, const float* W, const float* b,
                                       __nv_bfloat16* Wt, float* bp, int K, int C,
                                       int KPAD, int CPAD) {
    int tot = CPAD * KPAD;
    if (j < tot) {
        int cc = j / KPAD, kk = j - cc * KPAD;
        Wt[j] = __float2bfloat16((cc < C && kk < K) ? W[kk * C + cc] : 0.f);
    } else {
        int cc = j - tot;
        bp[cc] = (cc < C) ? b[cc] : 0.f;
    }
}

__global__ void k_merged(const int* __restrict__ ei, const int* __restrict__ batch,
                         const float* __restrict__ x,
                         const float* __restrict__ W1, const float* __restrict__ b1,
                         const float* __restrict__ W2, const float* __restrict__ b2,
                         const float* __restrict__ W3, const float* __restrict__ b3) {
    int i = blockIdx.x * blockDim.x + threadIdx.x;
    if (i < M0) {
        atomicAdd(&g_cnt[ei[NE + i]], 1);
    } else if (i < M1) {
        int j = i - M0;
        int bi = batch[j];
        int bprev = (j > 0) ? batch[j - 1] : -1;
        for (int g = bprev + 1; g <= bi; g++) g_goff[g] = j;
        if (j == NN - 1)
            for (int g = bi + 1; g <= NG; g++) g_goff[g] = NN;
    } else if (i < M2) {
        padw_t(i - M1, W1, b1, g_Wt1, g_bp1, 54, 54, 64, 64);
    } else if (i < M3) {
        padw_t(i - M2, W2, b2, g_Wt2, g_bp2, 54, 108, 64, 128);
    } else if (i < M4) {
        padw_t(i - M3, W3, b3, g_Wt3, g_bp3, 108, 216, 112, 224);
    } else if (i < M5) {
        int j = i - M4;
        int r = j >> 3, cw = (j & 7) * 8;
        __nv_bfloat16 tmp[8];
#pragma unroll
        for (int t = 0; t < 8; t++) {
            int c = cw + t;
            tmp[t] = __float2bfloat16((c < 54) ? x[r * 54 + c] : 0.f);
        }
        *(uint4*)&g_xpb[r * 64 + cw] = *(uint4*)tmp;
    }
}

// ---------------- segment allocator: one launch, unordered contiguous CSR --
// rowptr[i] = base of segment of length cnt[i]+1. Also zeroes g_fill.
__global__ void k_alloc() {
    __shared__ int p[256];
    __shared__ int base;
    int b = blockIdx.x, t = threadIdx.x;
    int i = b * 256 + t;
    int v = (i < NN) ? g_cnt[i] + 1 : 0;    // +1 self loop
    p[t] = v;
    __syncthreads();
    for (int off = 1; off < 256; off <<= 1) {
        int u = (t >= off) ? p[t - off] : 0;
        __syncthreads();
        p[t] += u;
        __syncthreads();
    }
    if (t == 255) base = atomicAdd(&g_total, p[255]);
    __syncthreads();
    if (i < NN) {
        g_rowptr[i] = p[t] - v + base;
        g_fill[i] = 0;
    }
}

__global__ void k_fill(const int* __restrict__ ei) {
    int i = blockIdx.x * blockDim.x + threadIdx.x;
    if (i >= NT_EDGE) return;
    int r, c;
    if (i < NE) { r = ei[i]; c = ei[NE + i]; }
    else        { r = c = i - NE; }
    float nrm = rsqrtf((float)(g_cnt[r] + 1) * (float)(g_cnt[c] + 1));
    int pos = g_rowptr[c] + atomicAdd(&g_fill[c], 1);
    g_edata[pos] = make_int2(r, __float_as_int(nrm));
}

// ---------------- aggregation (bf16 gather, fp32 acc, bf16 out) -----------
__device__ __forceinline__ void acc8(float acc[8], float nrm, uint4 t) {
    float2 f0 = __bfloat1622float2(*(__nv_bfloat162*)&t.x);
    float2 f1 = __bfloat1622float2(*(__nv_bfloat162*)&t.y);
    float2 f2 = __bfloat1622float2(*(__nv_bfloat162*)&t.z);
    float2 f3 = __bfloat1622float2(*(__nv_bfloat162*)&t.w);
    acc[0] += nrm * f0.x; acc[1] += nrm * f0.y;
    acc[2] += nrm * f1.x; acc[3] += nrm * f1.y;
    acc[4] += nrm * f2.x; acc[5] += nrm * f2.y;
    acc[6] += nrm * f3.x; acc[7] += nrm * f3.y;
}

__device__ __forceinline__ uint4 pack8(const float acc[8]) {
    uint4 r;
    *(__nv_bfloat162*)&r.x = __float22bfloat162_rn(make_float2(acc[0], acc[1]));
    *(__nv_bfloat162*)&r.y = __float22bfloat162_rn(make_float2(acc[2], acc[3]));
    *(__nv_bfloat162*)&r.z = __float22bfloat162_rn(make_float2(acc[4], acc[5]));
    *(__nv_bfloat162*)&r.w = __float22bfloat162_rn(make_float2(acc[6], acc[7]));
    return r;
}

// 64-bf16 rows (128B = 1 line). 8 edges/warp-iter. bf16 out rows stride 64.
__global__ void k_agg64b(const __nv_bfloat16* __restrict__ in,
                         __nv_bfloat16* __restrict__ out) {
    int w = (blockIdx.x * blockDim.x + threadIdx.x) >> 5;
    int lane = threadIdx.x & 31;
    if (w >= NN) return;
    int q = lane >> 3, sl = lane & 7;
    int e0 = g_rowptr[w];
    int e1 = e0 + g_cnt[w] + 1;
    float acc[8];
#pragma unroll
    for (int j = 0; j < 8; j++) acc[j] = 0.f;
    for (int e = e0; e < e1; e += 8) {
        int i0 = e + q, i1 = e + 4 + q;
        bool v0 = i0 < e1, v1 = i1 < e1;
        int2 ed0 = __ldg(&g_edata[v0 ? i0 : e]);
        int2 ed1 = __ldg(&g_edata[v1 ? i1 : e]);
        float n0 = v0 ? __int_as_float(ed0.y) : 0.f;
        float n1 = v1 ? __int_as_float(ed1.y) : 0.f;
        const uint4* s0 = (const uint4*)(in + (long)ed0.x * 64);
        const uint4* s1 = (const uint4*)(in + (long)ed1.x * 64);
        uint4 t0 = __ldg(&s0[sl]);
        uint4 t1 = __ldg(&s1[sl]);
        acc8(acc, n0, t0);
        acc8(acc, n1, t1);
    }
#pragma unroll
    for (int j = 0; j < 8; j++) {
        acc[j] += __shfl_xor_sync(0xffffffffu, acc[j], 8);
        acc[j] += __shfl_xor_sync(0xffffffffu, acc[j], 16);
    }
    if (q == 0)   // all 8 sl active: full 64-el row (cols 54-63 are zeros)
        ((uint4*)(out + (long)w * 64))[sl] = pack8(acc);
}

// 128-bf16 rows (real data 216B = 7 sectors of 8). 4 edges/warp-iter.
// Lanes 14,15 (pure-zero pad sectors) skip their loads. Out rows stride 112.
__global__ void k_agg128b(const __nv_bfloat16* __restrict__ in,
                          __nv_bfloat16* __restrict__ out) {
    int w = (blockIdx.x * blockDim.x + threadIdx.x) >> 5;
    int lane = threadIdx.x & 31;
    if (w >= NN) return;
    int half = lane >> 4, sl = lane & 15;
    bool act = sl < 14;
    int e0 = g_rowptr[w];
    int e1 = e0 + g_cnt[w] + 1;
    float acc[8];
#pragma unroll
    for (int j = 0; j < 8; j++) acc[j] = 0.f;
    for (int e = e0; e < e1; e += 4) {
        int i0 = e + half, i1 = e + 2 + half;
        bool v0 = i0 < e1, v1 = i1 < e1;
        int2 ed0 = __ldg(&g_edata[v0 ? i0 : e]);
        int2 ed1 = __ldg(&g_edata[v1 ? i1 : e]);
        float n0 = v0 ? __int_as_float(ed0.y) : 0.f;
        float n1 = v1 ? __int_as_float(ed1.y) : 0.f;
        if (act) {
            const uint4* s0 = (const uint4*)(in + (long)ed0.x * 128);
            const uint4* s1 = (const uint4*)(in + (long)ed1.x * 128);
            uint4 t0 = __ldg(&s0[sl]);
            uint4 t1 = __ldg(&s1[sl]);
            acc8(acc, n0, t0);
            acc8(acc, n1, t1);
        }
    }
#pragma unroll
    for (int j = 0; j < 8; j++)
        acc[j] += __shfl_xor_sync(0xffffffffu, acc[j], 16);
    if (half == 0 && act)   // 112-el row
        ((uint4*)(out + (long)w * 112))[sl] = pack8(acc);
}

// ---------------- bf16 tensor-core GEMM (m16n8k16), bf16 in/out ----------
__device__ __forceinline__ void mma_bf16(float c[4], const unsigned a[4], const unsigned b[2]) {
    asm volatile(
        "mma.sync.aligned.m16n8k16.row.col.f32.bf16.bf16.f32 "
        "{%0,%1,%2,%3}, {%4,%5,%6,%7}, {%8,%9}, {%0,%1,%2,%3};\n"
        : "+f"(c[0]), "+f"(c[1]), "+f"(c[2]), "+f"(c[3])
        : "r"(a[0]), "r"(a[1]), "r"(a[2]), "r"(a[3]), "r"(b[0]), "r"(b[1]));
}

// A: bf16 rows, contiguous stride == KPAD (64 or 112). Wt: bf16 [CPAD][KPAD].
// Block: 256 thr = 8 warps (2 M x 4 N); tile 64 x CPAD; warp 32 x CPAD/4.
template <int KPAD, int CPAD>
__global__ __launch_bounds__(256)
void k_gemm_bf16(const __nv_bfloat16* __restrict__ A, const __nv_bfloat16* __restrict__ Wt,
                 const float* __restrict__ bias, __nv_bfloat16* __restrict__ out) {
    extern __shared__ __nv_bfloat16 smh[];
    constexpr int ASTR = KPAD + 8;        // row strides: bank-conflict-free frags
    constexpr int NTILES = CPAD / 32;
    __nv_bfloat16* As = smh;              // [64][ASTR]
    __nv_bfloat16* Ws = smh + 64 * ASTR;  // [CPAD][ASTR]

    int tid = threadIdx.x;
    int w = tid >> 5, lane = tid & 31;
    int g = lane >> 2, ctg = lane & 3;
    int wm = w & 1, wn = w >> 1;
    int row0 = blockIdx.x * 64;

    // stage A (raw bf16 copy, rows contiguous)
    for (int i = tid * 8; i < 64 * KPAD; i += 256 * 8) {
        int r = i / KPAD, k = i - (i / KPAD) * KPAD;
        uint4 v = make_uint4(0u, 0u, 0u, 0u);
        if (row0 + r < NN) v = *(const uint4*)&A[(long)(row0 + r) * KPAD + k];
        *(uint4*)&As[r * ASTR + k] = v;
    }
    // stage Wt
    for (int i = tid * 8; i < CPAD * KPAD; i += 256 * 8) {
        int n = i / KPAD, k = i - (i / KPAD) * KPAD;
        *(uint4*)&Ws[n * ASTR + k] = *(const uint4*)&Wt[n * KPAD + k];
    }
    __syncthreads();

    float c[2][NTILES][4];
#pragma unroll
    for (int mt = 0; mt < 2; mt++)
#pragma unroll
        for (int nt = 0; nt < NTILES; nt++)
#pragma unroll
            for (int i = 0; i < 4; i++) c[mt][nt][i] = 0.f;

#pragma unroll
    for (int ks = 0; ks < KPAD; ks += 16) {
        unsigned a[2][4];
#pragma unroll
        for (int mt = 0; mt < 2; mt++) {
            int ar = wm * 32 + mt * 16;
            int kb = ks + 2 * ctg;
            a[mt][0] = *(const unsigned*)&As[(ar + g) * ASTR + kb];
            a[mt][1] = *(const unsigned*)&As[(ar + g + 8) * ASTR + kb];
            a[mt][2] = *(const unsigned*)&As[(ar + g) * ASTR + kb + 8];
            a[mt][3] = *(const unsigned*)&As[(ar + g + 8) * ASTR + kb + 8];
        }
        unsigned b[NTILES][2];
#pragma unroll
        for (int nt = 0; nt < NTILES; nt++) {
            int col = wn * (CPAD / 4) + nt * 8 + g;
            int kb = ks + 2 * ctg;
            b[nt][0] = *(const unsigned*)&Ws[col * ASTR + kb];
            b[nt][1] = *(const unsigned*)&Ws[col * ASTR + kb + 8];
        }
#pragma unroll
        for (int mt = 0; mt < 2; mt++)
#pragma unroll
            for (int nt = 0; nt < NTILES; nt++)
                mma_bf16(c[mt][nt], a[mt], b[nt]);
    }

#pragma unroll
    for (int mt = 0; mt < 2; mt++) {
        int r0 = row0 + wm * 32 + mt * 16 + g;
#pragma unroll
        for (int nt = 0; nt < NTILES; nt++) {
            int col = wn * (CPAD / 4) + nt * 8 + 2 * ctg;
            float b0 = bias[col], b1 = bias[col + 1];
            if (r0 < NN)
                *(__nv_bfloat162*)&out[(long)r0 * CPAD + col] =
                    __float22bfloat162_rn(make_float2(
                        fmaxf(c[mt][nt][0] + b0, 0.f), fmaxf(c[mt][nt][1] + b1, 0.f)));
            if (r0 + 8 < NN)
                *(__nv_bfloat162*)&out[(long)(r0 + 8) * CPAD + col] =
                    __float22bfloat162_rn(make_float2(
                        fmaxf(c[mt][nt][2] + b0, 0.f), fmaxf(c[mt][nt][3] + b1, 0.f)));
        }
    }
}

// ---------------- pooling (bf16 in, fp32 accumulate) ----------------
__global__ void k_pool() {    // grid NG, block 224
    int g = blockIdx.x, f = threadIdx.x;
    if (f >= 216) return;
    int v0 = g_goff[g], v1 = g_goff[g + 1];
    float s = 0.f;
    for (int v = v0; v < v1; v++) s += __bfloat162float(g_h3b[(long)v * 224 + f]);
    float cnt = (float)(v1 - v0);
    g_pool[g * 216 + f] = s / fmaxf(cnt, 1.f);
}

// ---------------- tiled MLP head (fp32) ----------------
__global__ __launch_bounds__(256) void k_mlp1(const float* __restrict__ Wf1,
                                              const float* __restrict__ bf1) {
    extern __shared__ float smm[];
    float* Pt = smm;            // [64][216]
    float* Wt = smm + 64 * 216; // [216][32]
    int b = blockIdx.x, t = threadIdx.x;
    int bi = b >> 5, bj = b & 31;
    int g0 = bi * 64, c0 = bj * 32;
    for (int i = t; i < 64 * 216; i += 256) {
        int r = i / 216, k = i - r * 216;
        Pt[i] = g_pool[(g0 + r) * 216 + k];
    }
    for (int i = t; i < 216 * 32; i += 256) {
        int k = i >> 5, c = i & 31;
        Wt[i] = Wf1[k * 1024 + c0 + c];
    }
    __syncthreads();
    int c = t & 31, rb = t >> 5;
    float acc[8];
#pragma unroll
    for (int j = 0; j < 8; j++) acc[j] = 0.f;
    for (int k = 0; k < 216; k++) {
        float wv = Wt[k * 32 + c];
#pragma unroll
        for (int j = 0; j < 8; j++)
            acc[j] += Pt[(rb + 8 * j) * 216 + k] * wv;
    }
    float bias = bf1[c0 + c];
#pragma unroll
    for (int j = 0; j < 8; j++)
        g_g1[(g0 + rb + 8 * j) * 1024 + c0 + c] = fmaxf(acc[j] + bias, 0.f);
}

__global__ __launch_bounds__(256) void k_mlp2(const float* __restrict__ Wf2,
                                              const float* __restrict__ bf2,
                                              float* __restrict__ out) {
    __shared__ float At[64 * 128];   // 32KB
    __shared__ float Wt[128 * 32];   // 16KB
    int b = blockIdx.x, t = threadIdx.x;
    int bi = b >> 2, bj = b & 3;
    int g0 = bi * 64, c0 = bj * 32;
    int c = t & 31, rb = t >> 5;
    float acc[8];
#pragma unroll
    for (int j = 0; j < 8; j++) acc[j] = 0.f;
    for (int k0 = 0; k0 < 1024; k0 += 128) {
        for (int i = t; i < 64 * 128; i += 256) {
            int r = i >> 7, k = i & 127;
            At[i] = g_g1[(g0 + r) * 1024 + k0 + k];
        }
        for (int i = t; i < 128 * 32; i += 256) {
            int k = i >> 5, cc = i & 31;
            Wt[i] = Wf2[(k0 + k) * 128 + c0 + cc];
        }
        __syncthreads();
        for (int k = 0; k < 128; k++) {
            float wv = Wt[k * 32 + c];
#pragma unroll
            for (int j = 0; j < 8; j++)
                acc[j] += At[(rb + 8 * j) * 128 + k] * wv;
        }
        __syncthreads();
    }
    float bias = bf2[c0 + c];
#pragma unroll
    for (int j = 0; j < 8; j++)
        out[(g0 + rb + 8 * j) * 128 + c0 + c] = acc[j] + bias;
}

// ---------------- launch ----------------
static int smem_bytes_bf16(int KPAD, int CPAD) {
    return (64 + CPAD) * (KPAD + 8) * 2;
}

extern "C" void kernel_launch(void* const* d_in, const int* in_sizes, int n_in,
                              void* d_out, int out_size) {
    const float* x     = (const float*)d_in[0];
    const int*   ei    = (const int*)d_in[1];
    const int*   batch = (const int*)d_in[2];
    const float* W1 = (const float*)d_in[3];
    const float* b1 = (const float*)d_in[4];
    const float* W2 = (const float*)d_in[5];
    const float* b2 = (const float*)d_in[6];
    const float* W3 = (const float*)d_in[7];
    const float* b3 = (const float*)d_in[8];
    const float* Wf1 = (const float*)d_in[9];
    const float* bf1 = (const float*)d_in[10];
    const float* Wf2 = (const float*)d_in[11];
    const float* bf2 = (const float*)d_in[12];
    float* out = (float*)d_out;

    float *bp1, *bp2, *bp3;
    __nv_bfloat16 *xpb, *h1b, *h2b, *h3b, *aggb, *Wt1, *Wt2, *Wt3;
    cudaGetSymbolAddress((void**)&xpb, g_xpb);
    cudaGetSymbolAddress((void**)&h1b, g_h1b);
    cudaGetSymbolAddress((void**)&h2b, g_h2b);
    cudaGetSymbolAddress((void**)&h3b, g_h3b);
    cudaGetSymbolAddress((void**)&aggb, g_aggb);
    cudaGetSymbolAddress((void**)&Wt1, g_Wt1);
    cudaGetSymbolAddress((void**)&Wt2, g_Wt2);
    cudaGetSymbolAddress((void**)&Wt3, g_Wt3);
    cudaGetSymbolAddress((void**)&bp1, g_bp1);
    cudaGetSymbolAddress((void**)&bp2, g_bp2);
    cudaGetSymbolAddress((void**)&bp3, g_bp3);

    cudaFuncSetAttribute(k_gemm_bf16<64, 64>,
                         cudaFuncAttributeMaxDynamicSharedMemorySize, smem_bytes_bf16(64, 64));
    cudaFuncSetAttribute(k_gemm_bf16<64, 128>,
                         cudaFuncAttributeMaxDynamicSharedMemorySize, smem_bytes_bf16(64, 128));
    cudaFuncSetAttribute(k_gemm_bf16<112, 224>,
                         cudaFuncAttributeMaxDynamicSharedMemorySize, smem_bytes_bf16(112, 224));
    int mlp1_smem = (64 * 216 + 216 * 32) * 4;
    cudaFuncSetAttribute(k_mlp1, cudaFuncAttributeMaxDynamicSharedMemorySize, mlp1_smem);

    k_zero<<<NBLK, 256>>>();
    k_merged<<<(M5 + 255) / 256, 256>>>(ei, batch, x, W1, b1, W2, b2, W3, b3);
    k_alloc<<<NBLK, 256>>>();
    k_fill<<<(NT_EDGE + 255) / 256, 256>>>(ei);

    int ablk = (NN * 32 + 255) / 256;
    int gblk = (NN + 63) / 64;
    // layer 1: aggregate xpb -> aggb (bf16,64), bf16 GEMM K=64 -> 64 + relu -> h1b
    k_agg64b<<<ablk, 256>>>(xpb, aggb);
    k_gemm_bf16<64, 64><<<gblk, 256, smem_bytes_bf16(64, 64)>>>(aggb, Wt1, bp1, h1b);
    // layer 2: aggregate h1b -> aggb (bf16,64), bf16 GEMM K=64 -> 128 + relu -> h2b
    k_agg64b<<<ablk, 256>>>(h1b, aggb);
    k_gemm_bf16<64, 128><<<gblk, 256, smem_bytes_bf16(64, 128)>>>(aggb, Wt2, bp2, h2b);
    // layer 3: aggregate h2b -> aggb (bf16,112), bf16 GEMM K=112 -> 224 + relu -> h3b
    k_agg128b<<<ablk, 256>>>(h2b, aggb);
    k_gemm_bf16<112, 224><<<gblk, 256, smem_bytes_bf16(112, 224)>>>(aggb, Wt3, bp3, h3b);

    k_pool<<<NG, 224>>>();
    k_mlp1<<<128, 256, mlp1_smem>>>(Wf1, bf1);
    k_mlp2<<<16, 256>>>(Wf2, bf2, out);
}